// round 15
// baseline (speedup 1.0000x reference)
#include <cuda_runtime.h>
#include <cstdint>

#define NNODES 50000
#define HID 32
#define NCLS 16
#define FIN 128
#define BUCKET 128            // max supported degree per node (Poisson(32): safe)

// packed dual-fp32 ops (Blackwell f32x2; one rounding per element)
#define ADDF32X2(acc, v) \
    asm("add.rn.f32x2 %0, %1, %2;" : "=l"(acc) : "l"(acc), "l"(v))
#define FMAF32X2(acc, v, s) \
    asm("fma.rn.f32x2 %0, %1, %2, %3;" : "=l"(acc) : "l"(v), "l"(s), "l"(acc))
#define PACK2(dd, u) \
    asm("mov.b64 %0, {%1, %1};" : "=l"(dd) : "r"(u))

// ---- scratch (__device__ globals; allocation-free contract) ----
__device__ __align__(16) int   g_deg[NNODES];
__device__ __align__(16) float g_dis[NNODES + 1];            // [NNODES] stays 0 (sentinel)
__device__ __align__(16) int   g_csr[NNODES * BUCKET];       // 25.6 MB
__device__ __align__(16) float g_z[(NNODES + 1) * HID];      // unscaled xw; +1 zero row
__device__ __align__(16) float g_z2[(NNODES + 1) * HID];     // layer-2 z; +1 zero row (never written)

// ---- side stream + events for capture-fork ----
static cudaStream_t g_s2;
static cudaEvent_t  g_evFork, g_evJoin;
namespace {
struct _StreamInit {
    _StreamInit() {
        cudaStreamCreateWithFlags(&g_s2, cudaStreamNonBlocking);
        cudaEventCreateWithFlags(&g_evFork, cudaEventDisableTiming);
        cudaEventCreateWithFlags(&g_evJoin, cudaEventDisableTiming);
    }
};
_StreamInit _streamInit;
}

// ---------------------------------------------------------------------------
__global__ void k_init() {
    int i = blockIdx.x * blockDim.x + threadIdx.x;
    if (i < NNODES) g_deg[i] = 0;
    if (i < HID) g_z[NNODES * HID + i] = 0.f;   // sentinel row (cheap)
}

// ---------------------------------------------------------------------------
// fused degree-count + bucket fill, 4 edges/thread via int4
// ---------------------------------------------------------------------------
__global__ void k_fill4(const int* __restrict__ src, const int* __restrict__ dst, int E4) {
    int i = blockIdx.x * blockDim.x + threadIdx.x;
    if (i >= E4) return;
    int4 s4 = ((const int4*)src)[i];
    int4 d4 = ((const int4*)dst)[i];
    int p;
    p = atomicAdd(&g_deg[d4.x], 1); if (p < BUCKET) g_csr[(d4.x << 7) + p] = s4.x;
    p = atomicAdd(&g_deg[d4.y], 1); if (p < BUCKET) g_csr[(d4.y << 7) + p] = s4.y;
    p = atomicAdd(&g_deg[d4.z], 1); if (p < BUCKET) g_csr[(d4.z << 7) + p] = s4.z;
    p = atomicAdd(&g_deg[d4.w], 1); if (p < BUCKET) g_csr[(d4.w << 7) + p] = s4.w;
}

__global__ void k_fill_tail(const int* __restrict__ src, const int* __restrict__ dst,
                            int start, int E) {
    int i = start + blockIdx.x * blockDim.x + threadIdx.x;
    if (i >= E) return;
    int d = dst[i];
    int pos = atomicAdd(&g_deg[d], 1);
    if (pos < BUCKET) g_csr[(d << 7) + pos] = src[i];
}

// dis[n] = rsqrt(deg+1); g_dis[NNODES] stays 0 from static init
__global__ void k_dis() {
    int i = blockIdx.x * blockDim.x + threadIdx.x;
    if (i < NNODES) g_dis[i] = rsqrtf((float)(g_deg[i] + 1));
}

// ---------------------------------------------------------------------------
// Layer-1 GEMM (UNSCALED): z[i] = x[i] @ W1; forked stream, || with CSR build
// ---------------------------------------------------------------------------
__global__ void k_gemm1u(const float* __restrict__ x, const float* __restrict__ W) {
    __shared__ float xs[64][FIN];
    __shared__ float Wst[HID][FIN + 4];
    int tid = threadIdx.x;
    int nbase = blockIdx.x * 64;

    for (int i = tid; i < FIN * HID; i += 256) {
        int k = i >> 5, c = i & 31;
        Wst[c][k] = W[i];
    }
    const float4* x4 = (const float4*)(x + (size_t)nbase * FIN);
    float4* xs4 = (float4*)&xs[0][0];
    for (int i = tid; i < 64 * FIN / 4; i += 256) {
        int node = nbase + (i >> 5);
        xs4[i] = (node < NNODES) ? x4[i] : make_float4(0.f, 0.f, 0.f, 0.f);
    }
    __syncthreads();

    int warp = tid >> 5, lane = tid & 31;
    int n0 = warp * 8;
    float acc[8];
#pragma unroll
    for (int j = 0; j < 8; j++) acc[j] = 0.f;
#pragma unroll 2
    for (int k4 = 0; k4 < FIN / 4; k4++) {
        float4 wv = *(const float4*)&Wst[lane][k4 * 4];
#pragma unroll
        for (int j = 0; j < 8; j++) {
            float4 v = *(const float4*)&xs[n0 + j][k4 * 4];
            acc[j] = fmaf(v.x, wv.x, fmaf(v.y, wv.y, fmaf(v.z, wv.z, fmaf(v.w, wv.w, acc[j]))));
        }
    }
#pragma unroll
    for (int j = 0; j < 8; j++) {
        int node = nbase + n0 + j;
        if (node < NNODES)
            g_z[node * HID + lane] = acc[j];
    }
}

// ---------------------------------------------------------------------------
// Fused agg1 + gemm2: warp per NODE PAIR.
//  acc[n] = sum_s xw[s]*dis[s]  (incl. self loop), per-edge dis via shuffle
//  h1[n]  = tanh(dis[n]*acc + b1)      (smem only, never hits global)
//  z2[n]  = dis[n]*(h1[n] @ W2)        -> g_z2
// ---------------------------------------------------------------------------
__global__ void __launch_bounds__(256) k_agg1g2(
        const float* __restrict__ b1, const float* __restrict__ W2) {
    __shared__ float W2s[HID][HID + 1];
    __shared__ float hrow[8][2][HID];

    for (int i = threadIdx.x; i < HID * HID; i += 256)
        W2s[i >> 5][i & 31] = W2[i];
    __syncthreads();

    int warp = threadIdx.x >> 5;
    int lane = threadIdx.x & 31;
    int n0 = (blockIdx.x * 8 + warp) * 2;    // grid = 3125 exact
    int n1 = n0 + 1;
    int which = lane >> 3;                   // 0..3: edge slot within step
    int c4 = lane & 7;                       // 16B channel-group index

    const ulonglong2* zv = (const ulonglong2*)g_z;   // 8 x 16B per row
    unsigned long long a01_0 = 0ull, a23_0 = 0ull;
    unsigned long long a01_1 = 0ull, a23_1 = 0ull;
    if (which == 0) {                        // self loops: xw[n]*dis[n]
        ulonglong2 s0 = __ldg(&zv[n0 * 8 + c4]);
        ulonglong2 s1 = __ldg(&zv[n1 * 8 + c4]);
        unsigned long long dd0, dd1;
        PACK2(dd0, __float_as_uint(__ldg(&g_dis[n0])));
        PACK2(dd1, __float_as_uint(__ldg(&g_dis[n1])));
        FMAF32X2(a01_0, s0.x, dd0);
        FMAF32X2(a23_0, s0.y, dd0);
        FMAF32X2(a01_1, s1.x, dd1);
        FMAF32X2(a23_1, s1.y, dd1);
    }

    int base0 = n0 << 7, base1 = n1 << 7;
    int cnt0 = min(__ldg(&g_deg[n0]), BUCKET);
    int cnt1 = min(__ldg(&g_deg[n1]), BUCKET);
    int pmax = (max(cnt0, cnt1) + 7) & ~7;

    for (int j = 0; j < pmax; j += 32) {
        int idx0 = NNODES, idx1 = NNODES;    // sentinel -> zero row, dis=0
        if (j + lane < cnt0) idx0 = g_csr[base0 + j + lane];
        if (j + lane < cnt1) idx1 = g_csr[base1 + j + lane];
        float ds0 = __ldg(&g_dis[idx0]);
        float ds1 = __ldg(&g_dis[idx1]);
        int lim = min(32, pmax - j);
        if (lim == 32) {
#pragma unroll
            for (int t = 0; t < 32; t += 4) {
                int s0 = __shfl_sync(0xffffffff, idx0, t + which);
                int s1 = __shfl_sync(0xffffffff, idx1, t + which);
                float d0 = __shfl_sync(0xffffffff, ds0, t + which);
                float d1 = __shfl_sync(0xffffffff, ds1, t + which);
                ulonglong2 v0 = __ldg(&zv[s0 * 8 + c4]);
                ulonglong2 v1 = __ldg(&zv[s1 * 8 + c4]);
                unsigned long long dd0, dd1;
                PACK2(dd0, __float_as_uint(d0));
                PACK2(dd1, __float_as_uint(d1));
                FMAF32X2(a01_0, v0.x, dd0);
                FMAF32X2(a23_0, v0.y, dd0);
                FMAF32X2(a01_1, v1.x, dd1);
                FMAF32X2(a23_1, v1.y, dd1);
            }
        } else {
            for (int t = 0; t < lim; t += 4) {
                int s0 = __shfl_sync(0xffffffff, idx0, t + which);
                int s1 = __shfl_sync(0xffffffff, idx1, t + which);
                float d0 = __shfl_sync(0xffffffff, ds0, t + which);
                float d1 = __shfl_sync(0xffffffff, ds1, t + which);
                ulonglong2 v0 = __ldg(&zv[s0 * 8 + c4]);
                ulonglong2 v1 = __ldg(&zv[s1 * 8 + c4]);
                unsigned long long dd0, dd1;
                PACK2(dd0, __float_as_uint(d0));
                PACK2(dd1, __float_as_uint(d1));
                FMAF32X2(a01_0, v0.x, dd0);
                FMAF32X2(a23_0, v0.y, dd0);
                FMAF32X2(a01_1, v1.x, dd1);
                FMAF32X2(a23_1, v1.y, dd1);
            }
        }
    }

    // reduce over the 4 edge-slot groups (packed)
#pragma unroll
    for (int m = 8; m <= 16; m <<= 1) {
        unsigned long long t;
        t = __shfl_xor_sync(0xffffffff, a01_0, m); ADDF32X2(a01_0, t);
        t = __shfl_xor_sync(0xffffffff, a23_0, m); ADDF32X2(a23_0, t);
        t = __shfl_xor_sync(0xffffffff, a01_1, m); ADDF32X2(a01_1, t);
        t = __shfl_xor_sync(0xffffffff, a23_1, m); ADDF32X2(a23_1, t);
    }

    // lanes 0-7 finish node0, lanes 8-15 finish node1: h1 = tanh(dis*acc + b1)
    {
        bool second = (lane >= 8);
        unsigned long long s01 = second ? a01_1 : a01_0;
        unsigned long long s23 = second ? a23_1 : a23_0;
        int cntx = second ? cnt1 : cnt0;

        float ax = __uint_as_float((unsigned)(s01 & 0xffffffffull));
        float ay = __uint_as_float((unsigned)(s01 >> 32));
        float az = __uint_as_float((unsigned)(s23 & 0xffffffffull));
        float aw = __uint_as_float((unsigned)(s23 >> 32));

        float dn = rsqrtf((float)(cntx + 1));
        float4 bv = __ldg(&((const float4*)b1)[c4]);
        float4 hv;
        hv.x = tanhf(fmaf(ax, dn, bv.x));
        hv.y = tanhf(fmaf(ay, dn, bv.y));
        hv.z = tanhf(fmaf(az, dn, bv.z));
        hv.w = tanhf(fmaf(aw, dn, bv.w));

        if (lane < 16)
            *(float4*)&hrow[warp][lane >> 3][c4 * 4] = hv;
    }
    __syncwarp();

    // gemm2 matvec: 32 lanes = 2 nodes x 16 channel-pairs (c and c+16)
    {
        int nn = lane >> 4, cb = lane & 15;
        float a0 = 0.f, a1 = 0.f;
#pragma unroll
        for (int k = 0; k < HID; k++) {
            float hk = hrow[warp][nn][k];
            a0 = fmaf(hk, W2s[k][cb], a0);
            a1 = fmaf(hk, W2s[k][cb + 16], a1);
        }
        int node = n0 + nn;
        float dnx = rsqrtf((float)((nn ? cnt1 : cnt0) + 1));
        g_z2[node * HID + cb]      = a0 * dnx;
        g_z2[node * HID + cb + 16] = a1 * dnx;
    }
}

// ---------------------------------------------------------------------------
// agg2: warp per NODE PAIR on scaled g_z2 (R8 config) + fused classifier.
// ---------------------------------------------------------------------------
__global__ void __launch_bounds__(256) k_agg2(
        const float* __restrict__ b, float* __restrict__ out,
        const float* __restrict__ Wc, const float* __restrict__ bc,
        float* __restrict__ out_cls) {
    __shared__ float Wcs[HID * NCLS];
    __shared__ float bcs[NCLS];
    __shared__ float hrow[8][2][HID];
    for (int i = threadIdx.x; i < HID * NCLS; i += 256) Wcs[i] = Wc[i];
    if (threadIdx.x < NCLS) bcs[threadIdx.x] = bc[threadIdx.x];
    __syncthreads();

    int warp = threadIdx.x >> 5;
    int lane = threadIdx.x & 31;
    int n0 = (blockIdx.x * 8 + warp) * 2;    // grid = 3125 exact
    int n1 = n0 + 1;
    int which = lane >> 3;
    int c4 = lane & 7;

    const ulonglong2* zv = (const ulonglong2*)g_z2;
    unsigned long long a01_0 = 0ull, a23_0 = 0ull;
    unsigned long long a01_1 = 0ull, a23_1 = 0ull;
    if (which == 0) {
        ulonglong2 s0 = __ldg(&zv[n0 * 8 + c4]);
        ulonglong2 s1 = __ldg(&zv[n1 * 8 + c4]);
        a01_0 = s0.x; a23_0 = s0.y;
        a01_1 = s1.x; a23_1 = s1.y;
    }

    int base0 = n0 << 7, base1 = n1 << 7;
    int cnt0 = min(__ldg(&g_deg[n0]), BUCKET);
    int cnt1 = min(__ldg(&g_deg[n1]), BUCKET);
    int pmax = (max(cnt0, cnt1) + 7) & ~7;

    for (int j = 0; j < pmax; j += 32) {
        int idx0 = NNODES, idx1 = NNODES;
        if (j + lane < cnt0) idx0 = g_csr[base0 + j + lane];
        if (j + lane < cnt1) idx1 = g_csr[base1 + j + lane];
        int lim = min(32, pmax - j);
        if (lim == 32) {
#pragma unroll
            for (int t = 0; t < 32; t += 4) {
                int s0 = __shfl_sync(0xffffffff, idx0, t + which);
                int s1 = __shfl_sync(0xffffffff, idx1, t + which);
                ulonglong2 v0 = __ldg(&zv[s0 * 8 + c4]);
                ulonglong2 v1 = __ldg(&zv[s1 * 8 + c4]);
                ADDF32X2(a01_0, v0.x);
                ADDF32X2(a23_0, v0.y);
                ADDF32X2(a01_1, v1.x);
                ADDF32X2(a23_1, v1.y);
            }
        } else {
            for (int t = 0; t < lim; t += 4) {
                int s0 = __shfl_sync(0xffffffff, idx0, t + which);
                int s1 = __shfl_sync(0xffffffff, idx1, t + which);
                ulonglong2 v0 = __ldg(&zv[s0 * 8 + c4]);
                ulonglong2 v1 = __ldg(&zv[s1 * 8 + c4]);
                ADDF32X2(a01_0, v0.x);
                ADDF32X2(a23_0, v0.y);
                ADDF32X2(a01_1, v1.x);
                ADDF32X2(a23_1, v1.y);
            }
        }
    }

#pragma unroll
    for (int m = 8; m <= 16; m <<= 1) {
        unsigned long long t;
        t = __shfl_xor_sync(0xffffffff, a01_0, m); ADDF32X2(a01_0, t);
        t = __shfl_xor_sync(0xffffffff, a23_0, m); ADDF32X2(a23_0, t);
        t = __shfl_xor_sync(0xffffffff, a01_1, m); ADDF32X2(a01_1, t);
        t = __shfl_xor_sync(0xffffffff, a23_1, m); ADDF32X2(a23_1, t);
    }

    bool second = (lane >= 8);
    unsigned long long s01 = second ? a01_1 : a01_0;
    unsigned long long s23 = second ? a23_1 : a23_0;
    int node = second ? n1 : n0;
    int cntx = second ? cnt1 : cnt0;

    float ax = __uint_as_float((unsigned)(s01 & 0xffffffffull));
    float ay = __uint_as_float((unsigned)(s01 >> 32));
    float az = __uint_as_float((unsigned)(s23 & 0xffffffffull));
    float aw = __uint_as_float((unsigned)(s23 >> 32));

    float dn = rsqrtf((float)(cntx + 1));
    float4 bv = __ldg(&((const float4*)b)[c4]);
    float4 hv;
    hv.x = tanhf(fmaf(ax, dn, bv.x));
    hv.y = tanhf(fmaf(ay, dn, bv.y));
    hv.z = tanhf(fmaf(az, dn, bv.z));
    hv.w = tanhf(fmaf(aw, dn, bv.w));

    if (lane < 16) {
        ((float4*)out)[node * 8 + c4] = hv;
        *(float4*)&hrow[warp][lane >> 3][c4 * 4] = hv;
    }
    __syncwarp();

    int nn = lane >> 4, c = lane & 15;
    float a = bcs[c];
#pragma unroll
    for (int k = 0; k < HID; k++)
        a = fmaf(hrow[warp][nn][k], Wcs[k * NCLS + c], a);
    out_cls[(n0 + nn) * NCLS + c] = a;
}

// ---------------------------------------------------------------------------
extern "C" void kernel_launch(void* const* d_in, const int* in_sizes, int n_in,
                              void* d_out, int out_size) {
    const float* x   = (const float*)d_in[0];
    const int*   ei  = (const int*)d_in[1];
    const float* W1  = (const float*)d_in[2];
    const float* b1  = (const float*)d_in[3];
    const float* W2  = (const float*)d_in[4];
    const float* b2  = (const float*)d_in[5];
    const float* Wc  = (const float*)d_in[6];
    const float* bc  = (const float*)d_in[7];

    const int E = in_sizes[1] / 2;
    const int* src = ei;
    const int* dst = ei + E;

    float* out_cls = (float*)d_out;                    // [N, 16]
    float* h2_out  = (float*)d_out + NNODES * NCLS;    // [N, 32]

    const int T = 256;
    const int E4 = E / 4;

    // --- fork: gemm1 (unscaled) runs concurrent with CSR build ---
    cudaEventRecord(g_evFork, 0);
    cudaStreamWaitEvent(g_s2, g_evFork, 0);
    k_gemm1u<<<(NNODES + 63) / 64, T, 0, g_s2>>>(x, W1);
    cudaEventRecord(g_evJoin, g_s2);

    // main stream: CSR build + dis
    k_init<<<(NNODES + T - 1) / T, T>>>();
    k_fill4<<<(E4 + T - 1) / T, T>>>(src, dst, E4);
    if (E % 4)
        k_fill_tail<<<1, T>>>(src, dst, E4 * 4, E);
    k_dis<<<(NNODES + T - 1) / T, T>>>();

    // join: need gemm1u's z before aggregating
    cudaStreamWaitEvent(0, g_evJoin, 0);

    // fused layer-1 agg + layer-2 gemm
    k_agg1g2<<<NNODES / 16, T>>>(b1, W2);

    // layer-2 agg + fused classifier
    k_agg2<<<NNODES / 16, T>>>(b2, h2_out, Wc, bc, out_cls);
}